// round 1
// baseline (speedup 1.0000x reference)
#include <cuda_runtime.h>
#include <math.h>

// ---------------- problem constants ----------------
#define C      768
#define NHEAD  12
#define HD     64
#define BATT   16      // attention batch = 16 x-tokens
#define TT     16      // temporal dim
#define NN     197     // tokens per frame (1 cls + 14*14)
#define HH     14
#define JTOT   (TT*NN)          // 3152 kv tokens per batch
#define NROWS_Y (256*NN)        // 50432 rows of y
#define DMLP   3072
#define JSPLIT 8
#define JCHUNK (JTOT/JSPLIT)    // 394

// ---------------- scratch (device globals; no allocs allowed) ----------------
__device__ float g_yn  [NROWS_Y * C];          // LN(y), layout [bt][n][c]
__device__ float g_yk  [BATT * JTOT * C];      // post-conv tokens, layout [b][j][c]
__device__ float g_xn  [BATT * C];
__device__ float g_q   [BATT * C];
__device__ float g_qt  [BATT * NHEAD * C];     // Wk^T q per head
__device__ float g_sc  [BATT * NHEAD * JTOT];  // scores -> probs (in place)
__device__ float g_part[JSPLIT * BATT * NHEAD * C];
__device__ float g_ybar[BATT * NHEAD * C];
__device__ float g_o   [BATT * C];
__device__ float g_x2  [BATT * C];
__device__ float g_h   [BATT * C];
__device__ float g_act [BATT * DMLP];

// ---------------- LayerNorm: one block per row of 768 ----------------
__global__ void ln_kernel(const float* __restrict__ in, const float* __restrict__ w,
                          const float* __restrict__ b, float* __restrict__ out) {
    __shared__ float rsh[C];
    __shared__ float red[256];
    long row = blockIdx.x;
    const float* r = in + row * C;
    int tid = threadIdx.x;
    float s = 0.f;
    for (int i = tid; i < C; i += 256) { float v = r[i]; rsh[i] = v; s += v; }
    red[tid] = s; __syncthreads();
    for (int o = 128; o > 0; o >>= 1) { if (tid < o) red[tid] += red[tid + o]; __syncthreads(); }
    float mean = red[0] * (1.0f / C);
    __syncthreads();
    float vs = 0.f;
    for (int i = tid; i < C; i += 256) { float d = rsh[i] - mean; vs += d * d; }
    red[tid] = vs; __syncthreads();
    for (int o = 128; o > 0; o >>= 1) { if (tid < o) red[tid] += red[tid + o]; __syncthreads(); }
    float rstd = rsqrtf(red[0] * (1.0f / C) + 1e-5f);
    float* ot = out + row * C;
    for (int i = tid; i < C; i += 256) ot[i] = (rsh[i] - mean) * rstd * w[i] + b[i];
}

// ---------------- depthwise 3x3x3 conv DPE + residual, reshuffle to [b][j][c] ----------------
__global__ void conv_dpe_kernel(const float* __restrict__ yn, const float* __restrict__ dw,
                                const float* __restrict__ db, float* __restrict__ yk) {
    int bt = blockIdx.x;               // 0..255
    int n  = blockIdx.y;               // 0..196
    int b = bt >> 4, t = bt & 15;
    int tid = threadIdx.x;             // 256
    long obase = ((long)(b * JTOT + t * NN + n)) * C;
    long ibase = ((long)bt * NN + n) * C;
    if (n == 0) {   // cls token passes through
        for (int k = 0; k < 3; k++) { int c = tid + k * 256; yk[obase + c] = yn[ibase + c]; }
        return;
    }
    int h = (n - 1) / HH, w = (n - 1) % HH;
    for (int k = 0; k < 3; k++) {
        int c = tid + k * 256;
        float acc = db[c];
        const float* wt = dw + c * 27;
        #pragma unroll
        for (int kt = 0; kt < 3; kt++) {
            int tt = t + kt - 1; if (tt < 0 || tt >= TT) continue;
            #pragma unroll
            for (int kh = 0; kh < 3; kh++) {
                int hh = h + kh - 1; if (hh < 0 || hh >= HH) continue;
                #pragma unroll
                for (int kw = 0; kw < 3; kw++) {
                    int ww = w + kw - 1; if (ww < 0 || ww >= HH) continue;
                    acc += wt[kt * 9 + kh * 3 + kw] *
                           yn[(((long)(b * TT + tt) * NN) + 1 + hh * HH + ww) * C + c];
                }
            }
        }
        yk[obase + c] = yn[ibase + c] + acc;
    }
}

// ---------------- generic warp-per-output matvec: out[b][e] = act(in[b]·W[e] + bias) (+res) ----------------
__global__ void matvec_kernel(const float* __restrict__ in, const float* __restrict__ W,
                              const float* __restrict__ bias, const float* __restrict__ residual,
                              float* __restrict__ out, int E, int Cin, int act) {
    extern __shared__ float insh[];
    int b = blockIdx.y, tid = threadIdx.x;
    for (int i = tid; i < Cin; i += blockDim.x) insh[i] = in[(long)b * Cin + i];
    __syncthreads();
    int warp = tid >> 5, lane = tid & 31;
    int e = blockIdx.x * 8 + warp;
    if (e >= E) return;
    const float* wr = W + (long)e * Cin;
    float s = 0.f;
    for (int c = lane; c < Cin; c += 32) s += insh[c] * wr[c];
    #pragma unroll
    for (int o = 16; o > 0; o >>= 1) s += __shfl_xor_sync(0xffffffffu, s, o);
    if (lane == 0) {
        float v = s + bias[e];
        if (act == 1) v = 0.5f * v * (1.0f + erff(v * 0.70710678118654752f));
        if (residual) v += residual[(long)b * E + e];
        out[(long)b * E + e] = v;
    }
}

// ---------------- q-tilde: qt[b][h][c] = sum_d q[b][h*64+d] * Wk[(C+h*64+d)][c] ----------------
__global__ void qt_kernel(const float* __restrict__ q, const float* __restrict__ ipw,
                          float* __restrict__ qt) {
    int h = blockIdx.x, b = blockIdx.y, tid = threadIdx.x;
    __shared__ float qsh[HD];
    if (tid < HD) qsh[tid] = q[b * C + h * HD + tid];
    __syncthreads();
    for (int k = 0; k < 3; k++) {
        int c = tid + k * 256;
        float s = 0.f;
        #pragma unroll 8
        for (int d = 0; d < HD; d++) s += qsh[d] * ipw[(long)(C + h * HD + d) * C + c];
        qt[(b * NHEAD + h) * C + c] = s;
    }
}

// ---------------- scores: s[b][h][j] = 0.125 * yk[b][j]·qt[b][h] (warp per j) ----------------
__global__ void scores_kernel(const float* __restrict__ yk, const float* __restrict__ qt,
                              float* __restrict__ sc) {
    __shared__ float qsh[NHEAD * C];  // 36 KB
    int b = blockIdx.y, tid = threadIdx.x;
    for (int i = tid; i < NHEAD * C; i += 256) qsh[i] = qt[b * NHEAD * C + i];
    __syncthreads();
    int warp = tid >> 5, lane = tid & 31;
    int j = blockIdx.x * 8 + warp;
    const float* row = yk + ((long)(b * JTOT + j)) * C;
    float acc[NHEAD];
    #pragma unroll
    for (int h = 0; h < NHEAD; h++) acc[h] = 0.f;
    for (int c = lane; c < C; c += 32) {
        float v = row[c];
        #pragma unroll
        for (int h = 0; h < NHEAD; h++) acc[h] += v * qsh[h * C + c];
    }
    #pragma unroll
    for (int h = 0; h < NHEAD; h++) {
        #pragma unroll
        for (int o = 16; o > 0; o >>= 1) acc[h] += __shfl_xor_sync(0xffffffffu, acc[h], o);
    }
    if (lane == 0) {
        #pragma unroll
        for (int h = 0; h < NHEAD; h++) sc[(b * NHEAD + h) * JTOT + j] = acc[h] * 0.125f;
    }
}

// ---------------- softmax over 3152, in place ----------------
__global__ void softmax_kernel(float* __restrict__ sc) {
    __shared__ float sh[JTOT];
    __shared__ float red[256];
    float* s = sc + (long)blockIdx.x * JTOT;
    int tid = threadIdx.x;
    float m = -1e30f;
    for (int j = tid; j < JTOT; j += 256) { float v = s[j]; sh[j] = v; m = fmaxf(m, v); }
    red[tid] = m; __syncthreads();
    for (int o = 128; o > 0; o >>= 1) { if (tid < o) red[tid] = fmaxf(red[tid], red[tid + o]); __syncthreads(); }
    m = red[0]; __syncthreads();
    float sum = 0.f;
    for (int j = tid; j < JTOT; j += 256) { float e = __expf(sh[j] - m); sh[j] = e; sum += e; }
    red[tid] = sum; __syncthreads();
    for (int o = 128; o > 0; o >>= 1) { if (tid < o) red[tid] += red[tid + o]; __syncthreads(); }
    float inv = 1.0f / red[0];
    for (int j = tid; j < JTOT; j += 256) s[j] = sh[j] * inv;
}

// ---------------- weighted sum partials: part[js][b][h][c] = sum_{j in chunk} p*yk ----------------
__global__ void wsum_kernel(const float* __restrict__ yk, const float* __restrict__ p,
                            float* __restrict__ part) {
    __shared__ float psh[NHEAD * JCHUNK];  // 18.9 KB
    int b = blockIdx.x, cc = blockIdx.y, js = blockIdx.z;
    int tid = threadIdx.x;
    int j0 = js * JCHUNK;
    for (int i = tid; i < NHEAD * JCHUNK; i += 256) {
        int h = i / JCHUNK, jj = i % JCHUNK;
        psh[i] = p[(b * NHEAD + h) * JTOT + j0 + jj];
    }
    __syncthreads();
    int c = cc * 256 + tid;
    float acc[NHEAD];
    #pragma unroll
    for (int h = 0; h < NHEAD; h++) acc[h] = 0.f;
    const float* base = yk + ((long)(b * JTOT + j0)) * C + c;
    for (int jj = 0; jj < JCHUNK; jj++) {
        float v = base[(long)jj * C];
        #pragma unroll
        for (int h = 0; h < NHEAD; h++) acc[h] += psh[h * JCHUNK + jj] * v;
    }
    #pragma unroll
    for (int h = 0; h < NHEAD; h++)
        part[(((long)js * BATT + b) * NHEAD + h) * C + c] = acc[h];
}

__global__ void reduce_part_kernel(const float* __restrict__ part, float* __restrict__ ybar) {
    int idx = blockIdx.x * 256 + threadIdx.x;  // < 16*12*768 = 147456
    if (idx >= BATT * NHEAD * C) return;
    float s = 0.f;
    #pragma unroll
    for (int js = 0; js < JSPLIT; js++) s += part[(long)js * BATT * NHEAD * C + idx];
    ybar[idx] = s;
}

// ---------------- attention out: o[b][e] = Wv[e]·ybar[b][e/64] + bv[e] ----------------
__global__ void attnout_kernel(const float* __restrict__ ybar, const float* __restrict__ ipw,
                               const float* __restrict__ ipb, float* __restrict__ o) {
    int b = blockIdx.y, tid = threadIdx.x;
    int warp = tid >> 5, lane = tid & 31;
    int e = blockIdx.x * 8 + warp;     // < 768
    int h = e >> 6;
    const float* wr = ipw + (long)(2 * C + e) * C;
    const float* yb = ybar + (b * NHEAD + h) * C;
    float s = 0.f;
    for (int c = lane; c < C; c += 32) s += wr[c] * yb[c];
    #pragma unroll
    for (int off = 16; off > 0; off >>= 1) s += __shfl_xor_sync(0xffffffffu, s, off);
    if (lane == 0) o[b * C + e] = s + ipb[2 * C + e];
}

// ---------------- launcher ----------------
extern "C" void kernel_launch(void* const* d_in, const int* in_sizes, int n_in,
                              void* d_out, int out_size) {
    const float* x    = (const float*)d_in[0];
    const float* y    = (const float*)d_in[1];
    const float* dpew = (const float*)d_in[3];
    const float* dpeb = (const float*)d_in[4];
    const float* ipw  = (const float*)d_in[5];
    const float* ipb  = (const float*)d_in[6];
    const float* outw = (const float*)d_in[7];
    const float* outb = (const float*)d_in[8];
    const float* ln1w = (const float*)d_in[9];
    const float* ln1b = (const float*)d_in[10];
    const float* ln2w = (const float*)d_in[11];
    const float* ln2b = (const float*)d_in[12];
    const float* ln3w = (const float*)d_in[13];
    const float* ln3b = (const float*)d_in[14];
    const float* fcw  = (const float*)d_in[15];
    const float* fcb  = (const float*)d_in[16];
    const float* prw  = (const float*)d_in[17];
    const float* prb  = (const float*)d_in[18];
    float* out = (float*)d_out;

    float *yn, *yk, *xn, *q, *qt, *sc, *part, *ybar, *o, *x2, *hbuf, *act;
    cudaGetSymbolAddress((void**)&yn,   g_yn);
    cudaGetSymbolAddress((void**)&yk,   g_yk);
    cudaGetSymbolAddress((void**)&xn,   g_xn);
    cudaGetSymbolAddress((void**)&q,    g_q);
    cudaGetSymbolAddress((void**)&qt,   g_qt);
    cudaGetSymbolAddress((void**)&sc,   g_sc);
    cudaGetSymbolAddress((void**)&part, g_part);
    cudaGetSymbolAddress((void**)&ybar, g_ybar);
    cudaGetSymbolAddress((void**)&o,    g_o);
    cudaGetSymbolAddress((void**)&x2,   g_x2);
    cudaGetSymbolAddress((void**)&hbuf, g_h);
    cudaGetSymbolAddress((void**)&act,  g_act);

    // 1. LN over y and x
    ln_kernel<<<NROWS_Y, 256>>>(y, ln3w, ln3b, yn);
    ln_kernel<<<BATT, 256>>>(x, ln1w, ln1b, xn);
    // 2. depthwise 3D conv positional encoding + residual, into [b][j][c]
    conv_dpe_kernel<<<dim3(256, NN), 256>>>(yn, dpew, dpeb, yk);
    // 3. q = xn @ Wq^T + bq   (Wq = first C rows of in_proj_w)
    matvec_kernel<<<dim3(C / 8, BATT), 256, C * 4>>>(xn, ipw, ipb, nullptr, q, C, C, 0);
    // 4. q-tilde = Wk^T q per head
    qt_kernel<<<dim3(NHEAD, BATT), 256>>>(q, ipw, qt);
    // 5. scores over all kv tokens
    scores_kernel<<<dim3(JTOT / 8, BATT), 256>>>(yk, qt, sc);
    // 6. softmax
    softmax_kernel<<<BATT * NHEAD, 256>>>(sc);
    // 7. weighted token sum (split over j, deterministic two-stage reduce)
    wsum_kernel<<<dim3(BATT, 3, JSPLIT), 256>>>(yk, sc, part);
    reduce_part_kernel<<<(BATT * NHEAD * C + 255) / 256, 256>>>(part, ybar);
    // 8. o = Wv ybar + bv
    attnout_kernel<<<dim3(C / 8, BATT), 256>>>(ybar, ipw, ipb, o);
    // 9. out proj + residual with x
    matvec_kernel<<<dim3(C / 8, BATT), 256, C * 4>>>(o, outw, outb, x, x2, C, C, 0);
    // 10. MLP
    ln_kernel<<<BATT, 256>>>(x2, ln2w, ln2b, hbuf);
    matvec_kernel<<<dim3(DMLP / 8, BATT), 256, C * 4>>>(hbuf, fcw, fcb, nullptr, act, DMLP, C, 1);
    matvec_kernel<<<dim3(C / 8, BATT), 256, DMLP * 4>>>(act, prw, prb, x2, out, C, DMLP, 0);
}

// round 2
// speedup vs baseline: 2.1182x; 2.1182x over previous
#include <cuda_runtime.h>
#include <math.h>

// ---------------- problem constants ----------------
#define C      768
#define NHEAD  12
#define HD     64
#define BATT   16      // attention batch = 16 x-tokens
#define TT     16      // temporal dim
#define NN     197     // tokens per frame (1 cls + 14*14)
#define HH     14
#define JTOT   (TT*NN)          // 3152 kv tokens per batch
#define NROWS_Y (256*NN)        // 50432 rows of y
#define DMLP   3072
#define JSPLIT 16
#define JCHUNK (JTOT/JSPLIT)    // 197

// ---------------- scratch (device globals; no allocs allowed) ----------------
__device__ float2 g_stats[NROWS_Y];            // per-row mean, rstd of y
__device__ float g_yk  [BATT * JTOT * C];      // post-conv tokens, layout [b][j][c]
__device__ float g_xn  [BATT * C];
__device__ float g_q   [BATT * C];
__device__ float g_qt  [BATT * NHEAD * C];     // Wk^T q per head
__device__ float g_sc  [BATT * NHEAD * JTOT];  // scores -> probs (in place)
__device__ float g_part[JSPLIT * BATT * NHEAD * C];
__device__ float g_ybar[BATT * NHEAD * C];
__device__ float g_o   [BATT * C];
__device__ float g_x2  [BATT * C];
__device__ float g_h   [BATT * C];
__device__ float g_act [BATT * DMLP];

// ---------------- per-row mean/rstd of y (warp per row, float4) ----------------
__global__ void rowstats_kernel(const float* __restrict__ y, float2* __restrict__ stats) {
    int row = blockIdx.x * 8 + (threadIdx.x >> 5);
    int lane = threadIdx.x & 31;
    if (row >= NROWS_Y) return;
    const float* r = y + (long)row * C;
    float s = 0.f, ss = 0.f;
    #pragma unroll
    for (int u = 0; u < 6; u++) {
        float4 v = *(const float4*)(r + (lane + u * 32) * 4);
        s  += v.x + v.y + v.z + v.w;
        ss += v.x * v.x + v.y * v.y + v.z * v.z + v.w * v.w;
    }
    #pragma unroll
    for (int o = 16; o > 0; o >>= 1) {
        s  += __shfl_xor_sync(0xffffffffu, s, o);
        ss += __shfl_xor_sync(0xffffffffu, ss, o);
    }
    if (lane == 0) {
        float mu = s * (1.0f / C);
        float var = ss * (1.0f / C) - mu * mu;
        float2 st; st.x = mu; st.y = rsqrtf(var + 1e-5f);
        stats[row] = st;
    }
}

// ---------------- cls token: normalize + copy into yk ----------------
__global__ void cls_kernel(const float* __restrict__ y, const float2* __restrict__ stats,
                           const float* __restrict__ lnw, const float* __restrict__ lnb,
                           float* __restrict__ yk) {
    int bt = blockIdx.x;                 // 0..255
    int b = bt >> 4, t = bt & 15;
    long ro = (long)bt * NN * C;         // row n=0
    float2 st = stats[bt * NN];
    int c4 = threadIdx.x;                // 0..191
    float4 raw = *(const float4*)(y + ro + c4 * 4);
    float4 lw = *(const float4*)(lnw + c4 * 4);
    float4 lb = *(const float4*)(lnb + c4 * 4);
    float4 o;
    o.x = (raw.x - st.x) * st.y * lw.x + lb.x;
    o.y = (raw.y - st.x) * st.y * lw.y + lb.y;
    o.z = (raw.z - st.x) * st.y * lw.z + lb.z;
    o.w = (raw.w - st.x) * st.y * lw.w + lb.w;
    *(float4*)(yk + ((long)(b * JTOT + t * NN)) * C + c4 * 4) = o;
}

// ---------------- fused LN + depthwise 3x3x3 conv + residual ----------------
#define CCH 64
#define TILE_F (196 * CCH)   // floats per slice = 12544
__global__ void conv_dpe_kernel(const float* __restrict__ y, const float2* __restrict__ stats,
                                const float* __restrict__ lnw, const float* __restrict__ lnb,
                                const float* __restrict__ dw, const float* __restrict__ db,
                                float* __restrict__ yk) {
    extern __shared__ float sm[];
    float* tile = sm;                        // 3*12544
    float* wsh  = tile + 3 * TILE_F;         // 64*27
    float* lwsh = wsh + 64 * 27;             // 64
    float* lbsh = lwsh + 64;                 // 64
    float* dbsh = lbsh + 64;                 // 64
    float2* ssh = (float2*)(dbsh + 64);      // 3*196 float2

    int b = blockIdx.x, t = blockIdx.y, cc = blockIdx.z * CCH;
    int tid = threadIdx.x;                   // 256

    for (int i = tid; i < 64 * 27; i += 256) wsh[i] = dw[(long)(cc + i / 27) * 27 + i % 27];
    if (tid < 64) { lwsh[tid] = lnw[cc + tid]; lbsh[tid] = lnb[cc + tid]; dbsh[tid] = db[cc + tid]; }
    #pragma unroll
    for (int s = 0; s < 3; s++) {
        int tt = t + s - 1; if (tt < 0 || tt >= TT) continue;
        int rbase = (b * TT + tt) * NN + 1;
        for (int i = tid; i < 196; i += 256) ssh[s * 196 + i] = stats[rbase + i];
    }
    __syncthreads();

    #pragma unroll
    for (int s = 0; s < 3; s++) {
        int tt = t + s - 1; if (tt < 0 || tt >= TT) continue;
        long base = ((long)((b * TT + tt) * NN + 1)) * C + cc;
        for (int i = tid; i < 196 * 16; i += 256) {
            int sp = i >> 4, v = i & 15;
            float4 raw = *(const float4*)(y + base + (long)sp * C + v * 4);
            float2 st = ssh[s * 196 + sp];
            float4 lw = *(const float4*)(lwsh + v * 4);
            float4 lb = *(const float4*)(lbsh + v * 4);
            float4 o;
            o.x = (raw.x - st.x) * st.y * lw.x + lb.x;
            o.y = (raw.y - st.x) * st.y * lw.y + lb.y;
            o.z = (raw.z - st.x) * st.y * lw.z + lb.z;
            o.w = (raw.w - st.x) * st.y * lw.w + lb.w;
            *(float4*)(tile + s * TILE_F + sp * CCH + v * 4) = o;
        }
    }
    __syncthreads();

    for (int item = tid; item < CCH * HH; item += 256) {
        int ch = item & 63, h = item >> 6;
        float wreg[27];
        #pragma unroll
        for (int q = 0; q < 27; q++) wreg[q] = wsh[ch * 27 + q];
        float bias = dbsh[ch];
        float acc[14];
        #pragma unroll
        for (int w = 0; w < 14; w++) acc[w] = bias;
        #pragma unroll
        for (int s = 0; s < 3; s++) {
            int tt = t + s - 1; if (tt < 0 || tt >= TT) continue;
            #pragma unroll
            for (int kh = 0; kh < 3; kh++) {
                int hh = h + kh - 1; if (hh < 0 || hh >= HH) continue;
                float row[14];
                #pragma unroll
                for (int w = 0; w < 14; w++) row[w] = tile[s * TILE_F + (hh * 14 + w) * CCH + ch];
                #pragma unroll
                for (int kw = 0; kw < 3; kw++) {
                    float wv = wreg[s * 9 + kh * 3 + kw];
                    #pragma unroll
                    for (int w = 0; w < 14; w++) {
                        int src = w + kw - 1;
                        if (src >= 0 && src < 14) acc[w] += wv * row[src];
                    }
                }
            }
        }
        long obase = ((long)(b * JTOT + t * NN + 1 + h * 14)) * C + cc + ch;
        #pragma unroll
        for (int w = 0; w < 14; w++) {
            float ctr = tile[TILE_F + (h * 14 + w) * CCH + ch];
            yk[obase + (long)w * C] = ctr + acc[w];
        }
    }
}

// ---------------- LayerNorm for small x rows ----------------
__global__ void ln_kernel(const float* __restrict__ in, const float* __restrict__ w,
                          const float* __restrict__ b, float* __restrict__ out) {
    __shared__ float rsh[C];
    __shared__ float red[256];
    long row = blockIdx.x;
    const float* r = in + row * C;
    int tid = threadIdx.x;
    float s = 0.f;
    for (int i = tid; i < C; i += 256) { float v = r[i]; rsh[i] = v; s += v; }
    red[tid] = s; __syncthreads();
    for (int o = 128; o > 0; o >>= 1) { if (tid < o) red[tid] += red[tid + o]; __syncthreads(); }
    float mean = red[0] * (1.0f / C);
    __syncthreads();
    float vs = 0.f;
    for (int i = tid; i < C; i += 256) { float d = rsh[i] - mean; vs += d * d; }
    red[tid] = vs; __syncthreads();
    for (int o = 128; o > 0; o >>= 1) { if (tid < o) red[tid] += red[tid + o]; __syncthreads(); }
    float rstd = rsqrtf(red[0] * (1.0f / C) + 1e-5f);
    float* ot = out + row * C;
    for (int i = tid; i < C; i += 256) ot[i] = (rsh[i] - mean) * rstd * w[i] + b[i];
}

// ---------------- generic warp-per-output matvec ----------------
__global__ void matvec_kernel(const float* __restrict__ in, const float* __restrict__ W,
                              const float* __restrict__ bias, const float* __restrict__ residual,
                              float* __restrict__ out, int E, int Cin, int act) {
    extern __shared__ float insh[];
    int b = blockIdx.y, tid = threadIdx.x;
    for (int i = tid; i < Cin; i += blockDim.x) insh[i] = in[(long)b * Cin + i];
    __syncthreads();
    int warp = tid >> 5, lane = tid & 31;
    int e = blockIdx.x * 8 + warp;
    if (e >= E) return;
    const float* wr = W + (long)e * Cin;
    float s = 0.f;
    for (int c = lane * 4; c < Cin; c += 128) {
        float4 wv = *(const float4*)(wr + c);
        float4 iv = *(const float4*)(insh + c);
        s += wv.x * iv.x + wv.y * iv.y + wv.z * iv.z + wv.w * iv.w;
    }
    #pragma unroll
    for (int o = 16; o > 0; o >>= 1) s += __shfl_xor_sync(0xffffffffu, s, o);
    if (lane == 0) {
        float v = s + bias[e];
        if (act == 1) v = 0.5f * v * (1.0f + erff(v * 0.70710678118654752f));
        if (residual) v += residual[(long)b * E + e];
        out[(long)b * E + e] = v;
    }
}

// ---------------- q-tilde ----------------
__global__ void qt_kernel(const float* __restrict__ q, const float* __restrict__ ipw,
                          float* __restrict__ qt) {
    int h = blockIdx.x, b = blockIdx.y, tid = threadIdx.x;
    __shared__ float qsh[HD];
    if (tid < HD) qsh[tid] = q[b * C + h * HD + tid];
    __syncthreads();
    for (int k = 0; k < 3; k++) {
        int c = tid + k * 256;
        float s = 0.f;
        #pragma unroll 8
        for (int d = 0; d < HD; d++) s += qsh[d] * ipw[(long)(C + h * HD + d) * C + c];
        qt[(b * NHEAD + h) * C + c] = s;
    }
}

// ---------------- scores: warp handles 4 j's, float4 ----------------
__global__ void scores_kernel(const float* __restrict__ yk, const float* __restrict__ qt,
                              float* __restrict__ sc) {
    __shared__ float qsh[NHEAD * C];
    int b = blockIdx.y, tid = threadIdx.x;
    for (int i = tid; i < NHEAD * C / 4; i += 256)
        ((float4*)qsh)[i] = ((const float4*)(qt + (long)b * NHEAD * C))[i];
    __syncthreads();
    int warp = tid >> 5, lane = tid & 31;
    int j0 = (blockIdx.x * 8 + warp) * 4;
    if (j0 >= JTOT) return;
    float acc[NHEAD][4];
    #pragma unroll
    for (int h = 0; h < NHEAD; h++)
        #pragma unroll
        for (int jj = 0; jj < 4; jj++) acc[h][jj] = 0.f;
    const float* rb = yk + ((long)b * JTOT + j0) * C;
    #pragma unroll
    for (int u = 0; u < 6; u++) {
        int c4 = lane + u * 32;
        float4 yv[4];
        #pragma unroll
        for (int jj = 0; jj < 4; jj++) yv[jj] = *(const float4*)(rb + (long)jj * C + c4 * 4);
        #pragma unroll
        for (int h = 0; h < NHEAD; h++) {
            float4 qv = *(const float4*)(qsh + h * C + c4 * 4);
            #pragma unroll
            for (int jj = 0; jj < 4; jj++)
                acc[h][jj] += qv.x * yv[jj].x + qv.y * yv[jj].y + qv.z * yv[jj].z + qv.w * yv[jj].w;
        }
    }
    #pragma unroll
    for (int h = 0; h < NHEAD; h++)
        #pragma unroll
        for (int jj = 0; jj < 4; jj++) {
            float v = acc[h][jj];
            #pragma unroll
            for (int o = 16; o > 0; o >>= 1) v += __shfl_xor_sync(0xffffffffu, v, o);
            if (lane == 0) sc[((long)b * NHEAD + h) * JTOT + j0 + jj] = v * 0.125f;
        }
}

// ---------------- softmax ----------------
__global__ void softmax_kernel(float* __restrict__ sc) {
    __shared__ float sh[JTOT];
    __shared__ float red[256];
    float* s = sc + (long)blockIdx.x * JTOT;
    int tid = threadIdx.x;
    float m = -1e30f;
    for (int j = tid; j < JTOT; j += 256) { float v = s[j]; sh[j] = v; m = fmaxf(m, v); }
    red[tid] = m; __syncthreads();
    for (int o = 128; o > 0; o >>= 1) { if (tid < o) red[tid] = fmaxf(red[tid], red[tid + o]); __syncthreads(); }
    m = red[0]; __syncthreads();
    float sum = 0.f;
    for (int j = tid; j < JTOT; j += 256) { float e = __expf(sh[j] - m); sh[j] = e; sum += e; }
    red[tid] = sum; __syncthreads();
    for (int o = 128; o > 0; o >>= 1) { if (tid < o) red[tid] += red[tid + o]; __syncthreads(); }
    float inv = 1.0f / red[0];
    for (int j = tid; j < JTOT; j += 256) s[j] = sh[j] * inv;
}

// ---------------- weighted sum partials ----------------
__global__ void wsum_kernel(const float* __restrict__ yk, const float* __restrict__ p,
                            float* __restrict__ part) {
    __shared__ float psh[NHEAD * JCHUNK];
    int b = blockIdx.x, js = blockIdx.y;
    int tid = threadIdx.x;                 // 192
    int j0 = js * JCHUNK;
    for (int i = tid; i < NHEAD * JCHUNK; i += 192) {
        int h = i / JCHUNK, jj = i % JCHUNK;
        psh[i] = p[((long)b * NHEAD + h) * JTOT + j0 + jj];
    }
    __syncthreads();
    float4 acc[NHEAD];
    #pragma unroll
    for (int h = 0; h < NHEAD; h++) { acc[h].x = acc[h].y = acc[h].z = acc[h].w = 0.f; }
    const float* base = yk + ((long)b * JTOT + j0) * C + tid * 4;
    for (int jj = 0; jj < JCHUNK; jj++) {
        float4 v = *(const float4*)(base + (long)jj * C);
        #pragma unroll
        for (int h = 0; h < NHEAD; h++) {
            float pw = psh[h * JCHUNK + jj];
            acc[h].x += pw * v.x; acc[h].y += pw * v.y;
            acc[h].z += pw * v.z; acc[h].w += pw * v.w;
        }
    }
    #pragma unroll
    for (int h = 0; h < NHEAD; h++)
        *(float4*)(part + (((long)js * BATT + b) * NHEAD + h) * C + tid * 4) = acc[h];
}

__global__ void reduce_part_kernel(const float* __restrict__ part, float* __restrict__ ybar) {
    int idx = blockIdx.x * 256 + threadIdx.x;
    if (idx >= BATT * NHEAD * C) return;
    float s = 0.f;
    #pragma unroll
    for (int js = 0; js < JSPLIT; js++) s += part[(long)js * BATT * NHEAD * C + idx];
    ybar[idx] = s;
}

// ---------------- attention out ----------------
__global__ void attnout_kernel(const float* __restrict__ ybar, const float* __restrict__ ipw,
                               const float* __restrict__ ipb, float* __restrict__ o) {
    int b = blockIdx.y, tid = threadIdx.x;
    int warp = tid >> 5, lane = tid & 31;
    int e = blockIdx.x * 8 + warp;
    int h = e >> 6;
    const float* wr = ipw + (long)(2 * C + e) * C;
    const float* yb = ybar + ((long)b * NHEAD + h) * C;
    float s = 0.f;
    for (int c = lane * 4; c < C; c += 128) {
        float4 wv = *(const float4*)(wr + c);
        float4 yv = *(const float4*)(yb + c);
        s += wv.x * yv.x + wv.y * yv.y + wv.z * yv.z + wv.w * yv.w;
    }
    #pragma unroll
    for (int off = 16; off > 0; off >>= 1) s += __shfl_xor_sync(0xffffffffu, s, off);
    if (lane == 0) o[b * C + e] = s + ipb[2 * C + e];
}

// ---------------- launcher ----------------
extern "C" void kernel_launch(void* const* d_in, const int* in_sizes, int n_in,
                              void* d_out, int out_size) {
    const float* x    = (const float*)d_in[0];
    const float* y    = (const float*)d_in[1];
    const float* dpew = (const float*)d_in[3];
    const float* dpeb = (const float*)d_in[4];
    const float* ipw  = (const float*)d_in[5];
    const float* ipb  = (const float*)d_in[6];
    const float* outw = (const float*)d_in[7];
    const float* outb = (const float*)d_in[8];
    const float* ln1w = (const float*)d_in[9];
    const float* ln1b = (const float*)d_in[10];
    const float* ln2w = (const float*)d_in[11];
    const float* ln2b = (const float*)d_in[12];
    const float* ln3w = (const float*)d_in[13];
    const float* ln3b = (const float*)d_in[14];
    const float* fcw  = (const float*)d_in[15];
    const float* fcb  = (const float*)d_in[16];
    const float* prw  = (const float*)d_in[17];
    const float* prb  = (const float*)d_in[18];
    float* out = (float*)d_out;

    float2* stats; float *yk, *xn, *q, *qt, *sc, *part, *ybar, *o, *x2, *hbuf, *act;
    cudaGetSymbolAddress((void**)&stats, g_stats);
    cudaGetSymbolAddress((void**)&yk,   g_yk);
    cudaGetSymbolAddress((void**)&xn,   g_xn);
    cudaGetSymbolAddress((void**)&q,    g_q);
    cudaGetSymbolAddress((void**)&qt,   g_qt);
    cudaGetSymbolAddress((void**)&sc,   g_sc);
    cudaGetSymbolAddress((void**)&part, g_part);
    cudaGetSymbolAddress((void**)&ybar, g_ybar);
    cudaGetSymbolAddress((void**)&o,    g_o);
    cudaGetSymbolAddress((void**)&x2,   g_x2);
    cudaGetSymbolAddress((void**)&hbuf, g_h);
    cudaGetSymbolAddress((void**)&act,  g_act);

    const int conv_smem = (3 * TILE_F + 64 * 27 + 64 * 3) * 4 + 3 * 196 * 8;
    cudaFuncSetAttribute(conv_dpe_kernel, cudaFuncAttributeMaxDynamicSharedMemorySize, conv_smem);

    rowstats_kernel<<<(NROWS_Y + 7) / 8, 256>>>(y, stats);
    cls_kernel<<<256, 192>>>(y, stats, ln3w, ln3b, yk);
    conv_dpe_kernel<<<dim3(BATT, TT, C / CCH), 256, conv_smem>>>(y, stats, ln3w, ln3b, dpew, dpeb, yk);
    ln_kernel<<<BATT, 256>>>(x, ln1w, ln1b, xn);
    matvec_kernel<<<dim3(C / 8, BATT), 256, C * 4>>>(xn, ipw, ipb, nullptr, q, C, C, 0);
    qt_kernel<<<dim3(NHEAD, BATT), 256>>>(q, ipw, qt);
    scores_kernel<<<dim3((JTOT / 4 + 7) / 8, BATT), 256>>>(yk, qt, sc);
    softmax_kernel<<<BATT * NHEAD, 256>>>(sc);
    wsum_kernel<<<dim3(BATT, JSPLIT), 192>>>(yk, sc, part);
    reduce_part_kernel<<<(BATT * NHEAD * C + 255) / 256, 256>>>(part, ybar);
    attnout_kernel<<<dim3(C / 8, BATT), 256>>>(ybar, ipw, ipb, o);
    matvec_kernel<<<dim3(C / 8, BATT), 256, C * 4>>>(o, outw, outb, x, x2, C, C, 0);
    ln_kernel<<<BATT, 256>>>(x2, ln2w, ln2b, hbuf);
    matvec_kernel<<<dim3(DMLP / 8, BATT), 256, C * 4>>>(hbuf, fcw, fcb, nullptr, act, DMLP, C, 1);
    matvec_kernel<<<dim3(C / 8, BATT), 256, DMLP * 4>>>(act, prw, prb, x2, out, C, DMLP, 0);
}